// round 8
// baseline (speedup 1.0000x reference)
#include <cuda_runtime.h>
#include <cuda_fp16.h>
#include <cstdint>

#define FEAT      2048
#define NPROBE    64
#define NGALLERY  256
#define NROWS     16384           // NPROBE * NGALLERY
#define NCLS      751
#define NPAD      768
#define BN_EPS    1e-5f

#define BM        128
#define BN        128
#define BK        64
#define KITERS    (FEAT / BK)     // 32
#define THREADS   256             // 8 warps, warp tile 64x32, 2 CTAs/SM
#define WSCALE    64.0f
#define WSCALE_INV (1.0f / 64.0f)

// 3-stage smem pipeline: per stage A 16KB + B 16KB = 32KB
#define STAGE_BYTES 32768
#define NSTAGES     3
#define SMEM_TOTAL  (NSTAGES * STAGE_BYTES)   // 96 KB -> 2 CTAs/SM

#define EPI_STRIDE  132           // fp32 words, bank-conflict-free restage

#define NPART 10

// ---------------- device scratch ----------------
__device__ __align__(16) float g_part[NPART * 4 * FEAT];
__device__ __align__(16) float g_scale[FEAT];
__device__ __align__(16) float g_mean[FEAT];
__device__ __align__(16) float g_cconst[NPAD];
__device__ __align__(16) __half g_W16[NPAD * FEAT];          // 3 MB
__device__ __align__(16) __half g_A16[(size_t)NROWS * FEAT]; // 64 MB

// ---------------- helpers ----------------
__device__ __forceinline__ uint32_t smem_u32(const void* p) {
    uint32_t a;
    asm("{ .reg .u64 t; cvta.to.shared.u64 t, %1; cvt.u32.u64 %0, t; }"
        : "=r"(a) : "l"(p));
    return a;
}
__device__ __forceinline__ uint32_t sw128(uint32_t off) {
    return off ^ ((off >> 3) & 0x70);
}
__device__ __forceinline__ void cp16(uint32_t dst, const void* src) {
    asm volatile("cp.async.cg.shared.global [%0], [%1], 16;"
                 :: "r"(dst), "l"(src) : "memory");
}
#define CP_COMMIT() asm volatile("cp.async.commit_group;" ::: "memory")
#define CP_WAIT1()  asm volatile("cp.async.wait_group 1;" ::: "memory")

__device__ __forceinline__ void ldsm4(uint32_t* r, uint32_t addr) {
    asm volatile("ldmatrix.sync.aligned.m8n8.x4.shared.b16 {%0,%1,%2,%3}, [%4];"
                 : "=r"(r[0]), "=r"(r[1]), "=r"(r[2]), "=r"(r[3]) : "r"(addr));
}
__device__ __forceinline__ void mma16816(float* c, const uint32_t* a,
                                         const uint32_t* b) {
    asm volatile(
        "mma.sync.aligned.m16n8k16.row.col.f32.f16.f16.f32 "
        "{%0,%1,%2,%3}, {%4,%5,%6,%7}, {%8,%9}, {%0,%1,%2,%3};"
        : "+f"(c[0]), "+f"(c[1]), "+f"(c[2]), "+f"(c[3])
        : "r"(a[0]), "r"(a[1]), "r"(a[2]), "r"(a[3]), "r"(b[0]), "r"(b[1]));
}

// ---------------- kernel 1a: partial moments ----------------
__global__ void stats_part_kernel(const float* __restrict__ probe,
                                  const float* __restrict__ gallery) {
    const int f = blockIdx.x * 256 + threadIdx.x;
    const int y = blockIdx.y;
    const float* src = (y < 2) ? probe : gallery;
    const int r0 = (y < 2) ? y * 32 : (y - 2) * 32;
    float s1 = 0.f, s2 = 0.f, s3 = 0.f, s4 = 0.f;
    #pragma unroll 8
    for (int r = 0; r < 32; r++) {
        float v = src[(size_t)(r0 + r) * FEAT + f];
        float v2 = v * v;
        s1 += v; s2 += v2; s3 += v2 * v; s4 += v2 * v2;
    }
    g_part[(y * 4 + 0) * FEAT + f] = s1;
    g_part[(y * 4 + 1) * FEAT + f] = s2;
    g_part[(y * 4 + 2) * FEAT + f] = s3;
    g_part[(y * 4 + 3) * FEAT + f] = s4;
}

// ---------------- kernel 1b: finalize BN stats ----------------
__global__ void stats_final_kernel(const float* __restrict__ gamma) {
    const int f = blockIdx.x * 256 + threadIdx.x;
    float sp1 = 0.f, sp2 = 0.f, sp3 = 0.f, sp4 = 0.f;
    float sg1 = 0.f, sg2 = 0.f, sg3 = 0.f, sg4 = 0.f;
    #pragma unroll
    for (int y = 0; y < 2; y++) {
        sp1 += g_part[(y * 4 + 0) * FEAT + f];
        sp2 += g_part[(y * 4 + 1) * FEAT + f];
        sp3 += g_part[(y * 4 + 2) * FEAT + f];
        sp4 += g_part[(y * 4 + 3) * FEAT + f];
    }
    #pragma unroll
    for (int y = 2; y < 10; y++) {
        sg1 += g_part[(y * 4 + 0) * FEAT + f];
        sg2 += g_part[(y * 4 + 1) * FEAT + f];
        sg3 += g_part[(y * 4 + 2) * FEAT + f];
        sg4 += g_part[(y * 4 + 3) * FEAT + f];
    }
    const float ip = 1.f / NPROBE, ig = 1.f / NGALLERY;
    float mp1 = sp1 * ip, mp2 = sp2 * ip, mp3 = sp3 * ip, mp4 = sp4 * ip;
    float mg1 = sg1 * ig, mg2 = sg2 * ig, mg3 = sg3 * ig, mg4 = sg4 * ig;
    float mean = mp2 + mg2 - 2.f * mp1 * mg1;
    float ed2  = mp4 - 4.f * mp3 * mg1 + 6.f * mp2 * mg2 - 4.f * mp1 * mg3 + mg4;
    float var  = ed2 - mean * mean;
    g_mean[f]  = mean;
    g_scale[f] = gamma[f] * rsqrtf(var + BN_EPS);
}

// ---------------- kernel 2: fused A16 build + W prep ----------------
__global__ void fused_prep_kernel(const float* __restrict__ probe,
                                  const float* __restrict__ gallery,
                                  const float* __restrict__ W,
                                  const float* __restrict__ beta,
                                  const float* __restrict__ bias) {
    const int bx = blockIdx.x;
    const int tid = threadIdx.x;
    if (bx < 1024) {
        const int i = bx >> 4;
        const int jc = bx & 15;
        const int f0 = tid * 8;
        float4 p0 = *(const float4*)&probe[(size_t)i * FEAT + f0];
        float4 p1 = *(const float4*)&probe[(size_t)i * FEAT + f0 + 4];
        float4 m0 = *(const float4*)&g_mean[f0];
        float4 m1 = *(const float4*)&g_mean[f0 + 4];
        #pragma unroll 4
        for (int jj = 0; jj < 16; jj++) {
            const int j = jc * 16 + jj;
            float4 gv0 = *(const float4*)&gallery[(size_t)j * FEAT + f0];
            float4 gv1 = *(const float4*)&gallery[(size_t)j * FEAT + f0 + 4];
            float d[8];
            d[0] = p0.x - gv0.x; d[0] = d[0] * d[0] - m0.x;
            d[1] = p0.y - gv0.y; d[1] = d[1] * d[1] - m0.y;
            d[2] = p0.z - gv0.z; d[2] = d[2] * d[2] - m0.z;
            d[3] = p0.w - gv0.w; d[3] = d[3] * d[3] - m0.w;
            d[4] = p1.x - gv1.x; d[4] = d[4] * d[4] - m1.x;
            d[5] = p1.y - gv1.y; d[5] = d[5] * d[5] - m1.y;
            d[6] = p1.z - gv1.z; d[6] = d[6] * d[6] - m1.z;
            d[7] = p1.w - gv1.w; d[7] = d[7] * d[7] - m1.w;
            __half h[8];
            #pragma unroll
            for (int k = 0; k < 8; k++) h[k] = __float2half_rn(d[k]);
            *(uint4*)&g_A16[(size_t)(i * NGALLERY + j) * FEAT + f0] = *(uint4*)h;
        }
    } else {
        const int c = bx - 1024;
        const int f0 = tid * 8;
        float acc = 0.f;
        float w[8];
        if (c < NCLS) {
            float4 w0 = *(const float4*)&W[(size_t)c * FEAT + f0];
            float4 w1 = *(const float4*)&W[(size_t)c * FEAT + f0 + 4];
            w[0] = w0.x; w[1] = w0.y; w[2] = w0.z; w[3] = w0.w;
            w[4] = w1.x; w[5] = w1.y; w[6] = w1.z; w[7] = w1.w;
        } else {
            #pragma unroll
            for (int k = 0; k < 8; k++) w[k] = 0.f;
        }
        __half h[8];
        #pragma unroll
        for (int k = 0; k < 8; k++) {
            float s = g_scale[f0 + k];
            h[k] = __float2half_rn(w[k] * s * WSCALE);
            acc += w[k] * beta[f0 + k];
        }
        *(uint4*)&g_W16[(size_t)c * FEAT + f0] = *(uint4*)h;
        #pragma unroll
        for (int o = 16; o > 0; o >>= 1)
            acc += __shfl_down_sync(0xFFFFFFFFu, acc, o);
        __shared__ float red[8];
        if ((tid & 31) == 0) red[tid >> 5] = acc;
        __syncthreads();
        if (tid == 0) {
            float t = 0.f;
            #pragma unroll
            for (int k = 0; k < 8; k++) t += red[k];
            g_cconst[c] = t + ((c < NCLS) ? bias[c] : 0.f);
        }
    }
}

// ---------------- kernel 3: fp16 HMMA GEMM, single-sync 3-stage ----------
// C[16384,768] = A16 * W16^T. CTA tile 128x128x64, 8 warps (2Mx4N, 64x32),
// 2 resident CTAs/SM. One __syncthreads per k-iter; loads issued at top.
// Odd CTAs rotate the k-order by 16 tiles to decorrelate co-resident CTAs.
__global__ void __launch_bounds__(THREADS, 2)
gemm_kernel(float* __restrict__ out) {
    extern __shared__ char smem[];
    const uint32_t sb = smem_u32(smem);
    const int tid = threadIdx.x;
    const int lid = tid & 31;
    const int wid = tid >> 5;

    const int ct = blockIdx.x;            // 0..5
    const int rt = blockIdx.y;            // 0..127
    const int n0 = rt * BM;
    const int c0 = ct * BN;
    const int koff = ((ct ^ rt) & 1) * (KITERS / 2);   // desync co-resident CTAs

    const int pr = tid >> 3;              // row base 0..31
    const int pu = tid & 7;               // 16B chunk in 128B row

    const int wm = wid >> 2;              // 0..1
    const int wn = wid & 3;               // 0..3
    const int mbase = wm * 64;
    const int nbase = wn * 32;
    const int a_row  = ((lid >> 3) & 1) * 8 + (lid & 7);
    const int a_colb = (lid >> 4) * 16;
    const int b_row  = (lid >> 4) * 8 + (lid & 7);
    const int b_colb = ((lid >> 3) & 1) * 16;

    float acc[4][4][4];
    #pragma unroll
    for (int im = 0; im < 4; im++)
        #pragma unroll
        for (int in = 0; in < 4; in++)
            #pragma unroll
            for (int r = 0; r < 4; r++) acc[im][in][r] = 0.f;

    // issue loads for pipeline position t (k-slice (t+koff)&31) into slot t%3
    auto issue = [&](int t) {
        const uint32_t st = (uint32_t)(t % NSTAGES) * STAGE_BYTES;
        const int k0 = ((t + koff) & (KITERS - 1)) * BK;
        #pragma unroll
        for (int c = 0; c < 4; c++) {
            int row = pr + c * 32;
            cp16(sb + st + sw128(row * 128 + pu * 16),
                 &g_A16[(size_t)(n0 + row) * FEAT + k0 + pu * 8]);
            cp16(sb + st + 16384 + sw128(row * 128 + pu * 16),
                 &g_W16[(size_t)(c0 + row) * FEAT + k0 + pu * 8]);
        }
    };

    issue(0); CP_COMMIT();
    issue(1); CP_COMMIT();

    for (int t = 0; t < KITERS; t++) {
        CP_WAIT1();            // position t resident (t+1 may pend)
        __syncthreads();       // data visible; slot (t+2)%3 free (all warps
                               // finished compute of position t-1)
        if (t + 2 < KITERS) issue(t + 2);
        CP_COMMIT();           // empty group at tail keeps count invariant

        const uint32_t abuf = sb + (uint32_t)(t % NSTAGES) * STAGE_BYTES;
        const uint32_t bbuf = abuf + 16384;
        #pragma unroll
        for (int ik = 0; ik < 4; ik++) {
            uint32_t a[4][4];
            #pragma unroll
            for (int im = 0; im < 4; im++)
                ldsm4(a[im], abuf +
                      sw128((mbase + im * 16 + a_row) * 128 + ik * 32 + a_colb));
            uint32_t b[8];
            #pragma unroll
            for (int nb = 0; nb < 2; nb++)
                ldsm4(&b[nb * 4], bbuf +
                      sw128((nbase + nb * 16 + b_row) * 128 + ik * 32 + b_colb));
            #pragma unroll
            for (int im = 0; im < 4; im++)
                #pragma unroll
                for (int in = 0; in < 4; in++)
                    mma16816(acc[im][in], a[im], &b[in * 2]);
        }
    }

    // ---- epilogue: restage through smem (conflict-free), coalesced stores --
    __syncthreads();           // all ldsm reads of the last stage complete
    float* stage = reinterpret_cast<float*>(smem);   // 128 x EPI_STRIDE fp32
    #pragma unroll
    for (int im = 0; im < 4; im++) {
        #pragma unroll
        for (int in = 0; in < 4; in++) {
            const int r = mbase + im * 16 + (lid >> 2);
            const int c = nbase + in * 8 + (lid & 3) * 2;
            stage[r * EPI_STRIDE + c]           = acc[im][in][0] * WSCALE_INV;
            stage[r * EPI_STRIDE + c + 1]       = acc[im][in][1] * WSCALE_INV;
            stage[(r + 8) * EPI_STRIDE + c]     = acc[im][in][2] * WSCALE_INV;
            stage[(r + 8) * EPI_STRIDE + c + 1] = acc[im][in][3] * WSCALE_INV;
        }
    }
    __syncthreads();
    const int col = c0 + (tid & 127);
    const int rhalf = (tid >> 7) * 64;          // 0 or 64
    if (col < NCLS) {
        const float cc = g_cconst[col];
        #pragma unroll 8
        for (int r = 0; r < 64; r++)
            out[(size_t)(n0 + rhalf + r) * NCLS + col] =
                stage[(rhalf + r) * EPI_STRIDE + (tid & 127)] + cc;
    }
}

// ---------------- launch ----------------
extern "C" void kernel_launch(void* const* d_in, const int* in_sizes, int n_in,
                              void* d_out, int out_size) {
    const float* probe   = (const float*)d_in[0];
    const float* gallery = (const float*)d_in[1];
    const float* gamma   = (const float*)d_in[2];
    const float* beta    = (const float*)d_in[3];
    const float* W       = (const float*)d_in[4];
    const float* bias    = (const float*)d_in[5];
    float* out = (float*)d_out;

    stats_part_kernel<<<dim3(8, 10), 256>>>(probe, gallery);
    stats_final_kernel<<<8, 256>>>(gamma);
    fused_prep_kernel<<<1792, 256>>>(probe, gallery, W, beta, bias);

    static bool attr_set = false;
    if (!attr_set) {
        cudaFuncSetAttribute(gemm_kernel,
                             cudaFuncAttributeMaxDynamicSharedMemorySize, SMEM_TOTAL);
        attr_set = true;
    }
    gemm_kernel<<<dim3(6, 128, 1), THREADS, SMEM_TOTAL>>>(out);
}

// round 9
// speedup vs baseline: 1.0334x; 1.0334x over previous
#include <cuda_runtime.h>
#include <cuda_fp16.h>
#include <cstdint>

#define FEAT      2048
#define NPROBE    64
#define NGALLERY  256
#define NROWS     16384           // NPROBE * NGALLERY
#define NCLS      751
#define NPAD      768
#define BN_EPS    1e-5f

#define BM        128
#define BN        64
#define BK        64
#define KITERS    (FEAT / BK)     // 32
#define THREADS   256             // 8 warps (4M x 2N), warp tile 32x32
#define WSCALE    64.0f
#define WSCALE_INV (1.0f / 64.0f)

// 3-stage smem pipeline: per stage A 16KB + B 8KB = 24KB -> 72KB, 3 CTAs/SM
#define STAGE_BYTES 24576
#define NSTAGES     3
#define SMEM_TOTAL  (NSTAGES * STAGE_BYTES)   // 73728 B

#define EPI_STRIDE  68            // fp32 words

#define NPART 10

// ---------------- device scratch ----------------
__device__ __align__(16) float g_part[NPART * 4 * FEAT];
__device__ __align__(16) float g_scale[FEAT];
__device__ __align__(16) float g_mean[FEAT];
__device__ __align__(16) float g_cconst[NPAD];
__device__ __align__(16) __half g_W16[NPAD * FEAT];          // 3 MB
__device__ __align__(16) __half g_A16[(size_t)NROWS * FEAT]; // 64 MB

// ---------------- helpers ----------------
__device__ __forceinline__ uint32_t smem_u32(const void* p) {
    uint32_t a;
    asm("{ .reg .u64 t; cvta.to.shared.u64 t, %1; cvt.u32.u64 %0, t; }"
        : "=r"(a) : "l"(p));
    return a;
}
__device__ __forceinline__ uint32_t sw128(uint32_t off) {
    return off ^ ((off >> 3) & 0x70);
}
__device__ __forceinline__ void cp16(uint32_t dst, const void* src) {
    asm volatile("cp.async.cg.shared.global [%0], [%1], 16;"
                 :: "r"(dst), "l"(src) : "memory");
}
#define CP_COMMIT() asm volatile("cp.async.commit_group;" ::: "memory")
#define CP_WAIT2()  asm volatile("cp.async.wait_group 2;" ::: "memory")

__device__ __forceinline__ void ldsm4(uint32_t* r, uint32_t addr) {
    asm volatile("ldmatrix.sync.aligned.m8n8.x4.shared.b16 {%0,%1,%2,%3}, [%4];"
                 : "=r"(r[0]), "=r"(r[1]), "=r"(r[2]), "=r"(r[3]) : "r"(addr));
}
__device__ __forceinline__ void mma16816(float* c, const uint32_t* a,
                                         const uint32_t* b) {
    asm volatile(
        "mma.sync.aligned.m16n8k16.row.col.f32.f16.f16.f32 "
        "{%0,%1,%2,%3}, {%4,%5,%6,%7}, {%8,%9}, {%0,%1,%2,%3};"
        : "+f"(c[0]), "+f"(c[1]), "+f"(c[2]), "+f"(c[3])
        : "r"(a[0]), "r"(a[1]), "r"(a[2]), "r"(a[3]), "r"(b[0]), "r"(b[1]));
}

// ---------------- kernel 1a: partial moments ----------------
__global__ void stats_part_kernel(const float* __restrict__ probe,
                                  const float* __restrict__ gallery) {
    const int f = blockIdx.x * 256 + threadIdx.x;
    const int y = blockIdx.y;
    const float* src = (y < 2) ? probe : gallery;
    const int r0 = (y < 2) ? y * 32 : (y - 2) * 32;
    float s1 = 0.f, s2 = 0.f, s3 = 0.f, s4 = 0.f;
    #pragma unroll 8
    for (int r = 0; r < 32; r++) {
        float v = src[(size_t)(r0 + r) * FEAT + f];
        float v2 = v * v;
        s1 += v; s2 += v2; s3 += v2 * v; s4 += v2 * v2;
    }
    g_part[(y * 4 + 0) * FEAT + f] = s1;
    g_part[(y * 4 + 1) * FEAT + f] = s2;
    g_part[(y * 4 + 2) * FEAT + f] = s3;
    g_part[(y * 4 + 3) * FEAT + f] = s4;
}

// ---------------- kernel 1b: finalize BN stats ----------------
__global__ void stats_final_kernel(const float* __restrict__ gamma) {
    const int f = blockIdx.x * 256 + threadIdx.x;
    float sp1 = 0.f, sp2 = 0.f, sp3 = 0.f, sp4 = 0.f;
    float sg1 = 0.f, sg2 = 0.f, sg3 = 0.f, sg4 = 0.f;
    #pragma unroll
    for (int y = 0; y < 2; y++) {
        sp1 += g_part[(y * 4 + 0) * FEAT + f];
        sp2 += g_part[(y * 4 + 1) * FEAT + f];
        sp3 += g_part[(y * 4 + 2) * FEAT + f];
        sp4 += g_part[(y * 4 + 3) * FEAT + f];
    }
    #pragma unroll
    for (int y = 2; y < 10; y++) {
        sg1 += g_part[(y * 4 + 0) * FEAT + f];
        sg2 += g_part[(y * 4 + 1) * FEAT + f];
        sg3 += g_part[(y * 4 + 2) * FEAT + f];
        sg4 += g_part[(y * 4 + 3) * FEAT + f];
    }
    const float ip = 1.f / NPROBE, ig = 1.f / NGALLERY;
    float mp1 = sp1 * ip, mp2 = sp2 * ip, mp3 = sp3 * ip, mp4 = sp4 * ip;
    float mg1 = sg1 * ig, mg2 = sg2 * ig, mg3 = sg3 * ig, mg4 = sg4 * ig;
    float mean = mp2 + mg2 - 2.f * mp1 * mg1;
    float ed2  = mp4 - 4.f * mp3 * mg1 + 6.f * mp2 * mg2 - 4.f * mp1 * mg3 + mg4;
    float var  = ed2 - mean * mean;
    g_mean[f]  = mean;
    g_scale[f] = gamma[f] * rsqrtf(var + BN_EPS);
}

// ---------------- kernel 2: fused A16 build + W prep ----------------
__global__ void fused_prep_kernel(const float* __restrict__ probe,
                                  const float* __restrict__ gallery,
                                  const float* __restrict__ W,
                                  const float* __restrict__ beta,
                                  const float* __restrict__ bias) {
    const int bx = blockIdx.x;
    const int tid = threadIdx.x;
    if (bx < 1024) {
        const int i = bx >> 4;
        const int jc = bx & 15;
        const int f0 = tid * 8;
        float4 p0 = *(const float4*)&probe[(size_t)i * FEAT + f0];
        float4 p1 = *(const float4*)&probe[(size_t)i * FEAT + f0 + 4];
        float4 m0 = *(const float4*)&g_mean[f0];
        float4 m1 = *(const float4*)&g_mean[f0 + 4];
        #pragma unroll 4
        for (int jj = 0; jj < 16; jj++) {
            const int j = jc * 16 + jj;
            float4 gv0 = *(const float4*)&gallery[(size_t)j * FEAT + f0];
            float4 gv1 = *(const float4*)&gallery[(size_t)j * FEAT + f0 + 4];
            float d[8];
            d[0] = p0.x - gv0.x; d[0] = d[0] * d[0] - m0.x;
            d[1] = p0.y - gv0.y; d[1] = d[1] * d[1] - m0.y;
            d[2] = p0.z - gv0.z; d[2] = d[2] * d[2] - m0.z;
            d[3] = p0.w - gv0.w; d[3] = d[3] * d[3] - m0.w;
            d[4] = p1.x - gv1.x; d[4] = d[4] * d[4] - m1.x;
            d[5] = p1.y - gv1.y; d[5] = d[5] * d[5] - m1.y;
            d[6] = p1.z - gv1.z; d[6] = d[6] * d[6] - m1.z;
            d[7] = p1.w - gv1.w; d[7] = d[7] * d[7] - m1.w;
            __half h[8];
            #pragma unroll
            for (int k = 0; k < 8; k++) h[k] = __float2half_rn(d[k]);
            *(uint4*)&g_A16[(size_t)(i * NGALLERY + j) * FEAT + f0] = *(uint4*)h;
        }
    } else {
        const int c = bx - 1024;
        const int f0 = tid * 8;
        float acc = 0.f;
        float w[8];
        if (c < NCLS) {
            float4 w0 = *(const float4*)&W[(size_t)c * FEAT + f0];
            float4 w1 = *(const float4*)&W[(size_t)c * FEAT + f0 + 4];
            w[0] = w0.x; w[1] = w0.y; w[2] = w0.z; w[3] = w0.w;
            w[4] = w1.x; w[5] = w1.y; w[6] = w1.z; w[7] = w1.w;
        } else {
            #pragma unroll
            for (int k = 0; k < 8; k++) w[k] = 0.f;
        }
        __half h[8];
        #pragma unroll
        for (int k = 0; k < 8; k++) {
            float s = g_scale[f0 + k];
            h[k] = __float2half_rn(w[k] * s * WSCALE);
            acc += w[k] * beta[f0 + k];
        }
        *(uint4*)&g_W16[(size_t)c * FEAT + f0] = *(uint4*)h;
        #pragma unroll
        for (int o = 16; o > 0; o >>= 1)
            acc += __shfl_down_sync(0xFFFFFFFFu, acc, o);
        __shared__ float red[8];
        if ((tid & 31) == 0) red[tid >> 5] = acc;
        __syncthreads();
        if (tid == 0) {
            float t = 0.f;
            #pragma unroll
            for (int k = 0; k < 8; k++) t += red[k];
            g_cconst[c] = t + ((c < NCLS) ? bias[c] : 0.f);
        }
    }
}

// ---------------- kernel 3: fp16 HMMA GEMM, 3 CTAs/SM ----------------
// C[16384,768] = A16 * W16^T. CTA tile 128x64x64, 8 warps (4M x 2N, 32x32),
// 3-stage cp.async pipeline, 3 resident CTAs per SM (24 warps).
__global__ void __launch_bounds__(THREADS, 3)
gemm_kernel(float* __restrict__ out) {
    extern __shared__ char smem[];
    const uint32_t sb = smem_u32(smem);
    const int tid = threadIdx.x;
    const int lid = tid & 31;
    const int wid = tid >> 5;

    const int ct = blockIdx.x;            // 0..11
    const int rt = blockIdx.y;            // 0..127
    const int n0 = rt * BM;
    const int c0 = ct * BN;

    // producers
    const int pr = tid >> 3;              // row base 0..31
    const int pu = tid & 7;               // 16B chunk in 128B row

    // consumers: warp grid 4 (M) x 2 (N), warp tile 32x32
    const int wm = wid >> 1;              // 0..3
    const int wn = wid & 1;               // 0..1
    const int mbase = wm * 32;
    const int nbase = wn * 32;
    const int a_row  = ((lid >> 3) & 1) * 8 + (lid & 7);
    const int a_colb = (lid >> 4) * 16;
    const int b_row  = (lid >> 4) * 8 + (lid & 7);
    const int b_colb = ((lid >> 3) & 1) * 16;

    float acc[2][4][4];
    #pragma unroll
    for (int im = 0; im < 2; im++)
        #pragma unroll
        for (int in = 0; in < 4; in++)
            #pragma unroll
            for (int r = 0; r < 4; r++) acc[im][in][r] = 0.f;

    auto issue = [&](int kt) {
        const uint32_t st = (uint32_t)(kt % NSTAGES) * STAGE_BYTES;
        const int k0 = kt * BK;
        // A tile: 128 rows x 128B (4 chunks/thread)
        #pragma unroll
        for (int c = 0; c < 4; c++) {
            int row = pr + c * 32;
            cp16(sb + st + sw128(row * 128 + pu * 16),
                 &g_A16[(size_t)(n0 + row) * FEAT + k0 + pu * 8]);
        }
        // B tile: 64 rows x 128B (2 chunks/thread)
        #pragma unroll
        for (int c = 0; c < 2; c++) {
            int row = pr + c * 32;
            cp16(sb + st + 16384 + sw128(row * 128 + pu * 16),
                 &g_W16[(size_t)(c0 + row) * FEAT + k0 + pu * 8]);
        }
    };

    issue(0); CP_COMMIT();
    issue(1); CP_COMMIT();
    issue(2); CP_COMMIT();

    for (int kt = 0; kt < KITERS; kt++) {
        CP_WAIT2();            // stage kt resident (2 newer may pend)
        __syncthreads();

        const uint32_t abuf = sb + (uint32_t)(kt % NSTAGES) * STAGE_BYTES;
        const uint32_t bbuf = abuf + 16384;
        #pragma unroll
        for (int ik = 0; ik < 4; ik++) {
            uint32_t a[2][4];
            #pragma unroll
            for (int im = 0; im < 2; im++)
                ldsm4(a[im], abuf +
                      sw128((mbase + im * 16 + a_row) * 128 + ik * 32 + a_colb));
            uint32_t b[8];
            #pragma unroll
            for (int nb = 0; nb < 2; nb++)
                ldsm4(&b[nb * 4], bbuf +
                      sw128((nbase + nb * 16 + b_row) * 128 + ik * 32 + b_colb));
            #pragma unroll
            for (int im = 0; im < 2; im++)
                #pragma unroll
                for (int in = 0; in < 4; in++)
                    mma16816(acc[im][in], a[im], &b[in * 2]);
        }

        __syncthreads();       // reads of stage kt done; buffer reusable
        if (kt + 3 < KITERS) issue(kt + 3);
        CP_COMMIT();           // keep group-count invariant near the tail
    }

    // ---- epilogue: restage through smem, coalesced row stores ----
    float* stage = reinterpret_cast<float*>(smem);   // 128 x EPI_STRIDE fp32
    #pragma unroll
    for (int im = 0; im < 2; im++) {
        #pragma unroll
        for (int in = 0; in < 4; in++) {
            const int r = mbase + im * 16 + (lid >> 2);
            const int c = nbase + in * 8 + (lid & 3) * 2;
            stage[r * EPI_STRIDE + c]           = acc[im][in][0] * WSCALE_INV;
            stage[r * EPI_STRIDE + c + 1]       = acc[im][in][1] * WSCALE_INV;
            stage[(r + 8) * EPI_STRIDE + c]     = acc[im][in][2] * WSCALE_INV;
            stage[(r + 8) * EPI_STRIDE + c + 1] = acc[im][in][3] * WSCALE_INV;
        }
    }
    __syncthreads();
    const int col = c0 + (tid & 63);
    const int rbase = (tid >> 6) * 32;          // 0,32,64,96
    if (col < NCLS) {
        const float cc = g_cconst[col];
        #pragma unroll 8
        for (int r = 0; r < 32; r++)
            out[(size_t)(n0 + rbase + r) * NCLS + col] =
                stage[(rbase + r) * EPI_STRIDE + (tid & 63)] + cc;
    }
}

// ---------------- launch ----------------
extern "C" void kernel_launch(void* const* d_in, const int* in_sizes, int n_in,
                              void* d_out, int out_size) {
    const float* probe   = (const float*)d_in[0];
    const float* gallery = (const float*)d_in[1];
    const float* gamma   = (const float*)d_in[2];
    const float* beta    = (const float*)d_in[3];
    const float* W       = (const float*)d_in[4];
    const float* bias    = (const float*)d_in[5];
    float* out = (float*)d_out;

    stats_part_kernel<<<dim3(8, 10), 256>>>(probe, gallery);
    stats_final_kernel<<<8, 256>>>(gamma);
    fused_prep_kernel<<<1792, 256>>>(probe, gallery, W, beta, bias);

    static bool attr_set = false;
    if (!attr_set) {
        cudaFuncSetAttribute(gemm_kernel,
                             cudaFuncAttributeMaxDynamicSharedMemorySize, SMEM_TOTAL);
        attr_set = true;
    }
    gemm_kernel<<<dim3(12, 128, 1), THREADS, SMEM_TOTAL>>>(out);
}